// round 9
// baseline (speedup 1.0000x reference)
#include <cuda_runtime.h>
#include <cuda_fp16.h>
#include <cstdint>

// ============================================================================
// DenseAttention via Gram reassociation:
//   G[b,q]  = X_{b,q}^T X_{b,q}             (symmetric => compute 3 of 4 tiles)
//   T[b,a,q]= (1024*W_{a,q}) @ G[b,q]
//   Pq^T    = (1024*C_{a,q})-layout @ T^T ;  P^T[b,a] = 2^-10 * sum_q Pq^T
//   out     = 2^-10 * X_{b,a} @ P[b,a]
// Single-pass fp16, fp32 accumulate (rel_err 5.25e-4, calibrated R7/R8).
// R9: 64x128 tiles, 256 threads (warp tile 32x32), smem 102KB/CTA =>
//     2 CTAs = 16 warps resident per SM; grids >= 256 CTAs. TLP hides the
//     LDSM/HMMA dependency stalls that pinned issue% at 12.
// ============================================================================

#define HH 65536

// ---------------- scratch (static device globals; no allocation) ------------
__device__ __align__(256) __half g_Xt[8 * 256 * 2048];      // [bq][f][t]
__device__ __align__(256) __half g_Xnt[2 * 2048 * 1024];    // [b][t][e]
__device__ __align__(256) __half g_Wc[16 * HH];             // [aq][e][f] *1024
__device__ __align__(256) __half g_Ct[16 * HH];             // [aq][g'][g] *1024
__device__ __align__(256) float  g_Gpart[8 * 8 * 3 * 16384];// [chunk][bq][tile]
__device__ __align__(256) __half g_G[8 * HH];               // [bq][f][g]
__device__ __align__(256) __half g_T[32 * HH];              // [baq][e][g]
__device__ __align__(256) float  g_Pq[32 * HH];             // [baq][g'][e]
__device__ __align__(256) __half g_Pt[8 * HH];              // [ba][g'][e]

// ---------------- PTX helpers ------------------------------------------------
__device__ __forceinline__ uint32_t smem_u32(const void* p) {
    uint32_t a;
    asm("{ .reg .u64 t; cvta.to.shared.u64 t, %1; cvt.u32.u64 %0, t; }" : "=r"(a) : "l"(p));
    return a;
}
__device__ __forceinline__ void cpa16(uint32_t s, const void* g) {
    asm volatile("cp.async.cg.shared.global [%0], [%1], 16;" :: "r"(s), "l"(g));
}
#define CP_COMMIT() asm volatile("cp.async.commit_group;" ::: "memory")
#define CP_WAIT(n)  asm volatile("cp.async.wait_group %0;" :: "n"(n) : "memory")

#define LDSM_X4(r, addr) \
    asm volatile("ldmatrix.sync.aligned.m8n8.x4.shared.b16 {%0,%1,%2,%3}, [%4];" \
        : "=r"((r)[0]), "=r"((r)[1]), "=r"((r)[2]), "=r"((r)[3]) : "r"(addr))

#define MMA_F16(d, a, b0, b1) \
    asm volatile("mma.sync.aligned.m16n8k16.row.col.f32.f16.f16.f32 " \
        "{%0,%1,%2,%3}, {%4,%5,%6,%7}, {%8,%9}, {%0,%1,%2,%3};" \
        : "+f"((d)[0]), "+f"((d)[1]), "+f"((d)[2]), "+f"((d)[3]) \
        : "r"((a)[0]), "r"((a)[1]), "r"((a)[2]), "r"((a)[3]), "r"(b0), "r"(b1))

__device__ __forceinline__ uint2 pack4H(float4 v) {
    union { __half b[4]; uint2 u; } Hq;
    Hq.b[0] = __float2half_rn(v.x); Hq.b[1] = __float2half_rn(v.y);
    Hq.b[2] = __float2half_rn(v.z); Hq.b[3] = __float2half_rn(v.w);
    return Hq.u;
}

// ============================================================================
// 64x128 tile GEMM, 256 threads (8 warps: 2M x 4N, warp tile 32x32).
// K multiple of 128 (BK=128 double-buffered), fp16 single-pass, fp32 accum.
// SMEM/buffer: A 64x272 = 17408 + B 128x272 = 34816 => 52224; x2 = 104448.
// 104448 B/CTA => 2 CTAs (16 warps) per SM.
// EPI 0: fp32*scale -> Cf.   EPI 1: fp16 -> Ch.
// ============================================================================
#define ROWB   272
#define T_A    0
#define T_B    17408
#define BUFSZ  52224
#define SMEM_DYN (2 * BUFSZ)

template <int EPI>
__device__ __forceinline__ void gemm_body(
    const __half* __restrict__ A, int lda,
    const __half* __restrict__ B, int ldb,
    int K, float* __restrict__ Cf, __half* __restrict__ Ch, int ldc,
    float outScale)
{
    extern __shared__ char smem[];
    const uint32_t sb  = smem_u32(smem);
    const int tid  = threadIdx.x;
    const int lane = tid & 31;
    const int wid  = tid >> 5;
    const int m0   = (wid & 1) * 32;      // 2 M-warps
    const int n0   = (wid >> 1) * 32;     // 4 N-warps

    const uint32_t aoff = (uint32_t)(m0 + (lane & 15)) * ROWB + ((lane >> 4) << 4);
    const uint32_t boff = (uint32_t)(n0 + ((lane >> 4) << 3) + (lane & 7)) * ROWB
                        + ((lane & 8) ? 16u : 0u);

    float acc[2][4][4];
#pragma unroll
    for (int i = 0; i < 2; i++)
#pragma unroll
        for (int j = 0; j < 4; j++)
#pragma unroll
            for (int r = 0; r < 4; r++) acc[i][j][r] = 0.0f;

    auto load_chunk = [&](int c) {
        const uint32_t bo = sb + (uint32_t)(c & 1) * BUFSZ;
        const int k0 = c << 7;
        // A: 64 rows x 16 vec16 = 1024 -> 4 iters x 256 thr
#pragma unroll
        for (int i = 0; i < 4; i++) {
            int v = i * 256 + tid;
            int r = v >> 4, j = v & 15;
            cpa16(bo + T_A + (uint32_t)r * ROWB + (uint32_t)j * 16,
                  A + (size_t)r * lda + k0 + j * 8);
        }
        // B: 128 rows x 16 vec16 = 2048 -> 8 iters x 256 thr
#pragma unroll
        for (int i = 0; i < 8; i++) {
            int v = i * 256 + tid;
            int r = v >> 4, j = v & 15;
            cpa16(bo + T_B + (uint32_t)r * ROWB + (uint32_t)j * 16,
                  B + (size_t)r * ldb + k0 + j * 8);
        }
    };

    const int NC = K >> 7;
    load_chunk(0);
    CP_COMMIT();

#pragma unroll 1
    for (int c = 0; c < NC; c++) {
        if (c < NC - 1) { load_chunk(c + 1); CP_COMMIT(); CP_WAIT(1); }
        else            { CP_WAIT(0); }
        __syncthreads();

        const uint32_t bo = sb + (uint32_t)(c & 1) * BUFSZ;
        const uint32_t aP = bo + T_A + aoff;
        const uint32_t bP = bo + T_B + boff;

#pragma unroll
        for (int ks = 0; ks < 8; ks++) {
            const uint32_t ko = (uint32_t)ks * 32;
            uint32_t a0[4], a1[4];
            LDSM_X4(a0, aP + ko);
            LDSM_X4(a1, aP + 16 * ROWB + ko);
            uint32_t br[2][4];
            LDSM_X4(br[0], bP + ko);
            LDSM_X4(br[1], bP + 16 * ROWB + ko);
#pragma unroll
            for (int j = 0; j < 4; j++)
                MMA_F16(acc[0][j], a0, br[j >> 1][(j & 1) * 2], br[j >> 1][(j & 1) * 2 + 1]);
#pragma unroll
            for (int j = 0; j < 4; j++)
                MMA_F16(acc[1][j], a1, br[j >> 1][(j & 1) * 2], br[j >> 1][(j & 1) * 2 + 1]);
        }
        __syncthreads();
    }

    // ---- epilogue ----
    const int rr = lane >> 2;
    const int cc = (lane & 3) * 2;
#pragma unroll
    for (int i = 0; i < 2; i++) {
#pragma unroll
        for (int j = 0; j < 4; j++) {
            const int row = m0 + i * 16 + rr;
            const int col = n0 + j * 8 + cc;
            if (EPI == 0) {
                float* p = Cf + (size_t)row * ldc + col;
                *(float2*)p = make_float2(acc[i][j][0] * outScale, acc[i][j][1] * outScale);
                *(float2*)(p + (size_t)8 * ldc) =
                    make_float2(acc[i][j][2] * outScale, acc[i][j][3] * outScale);
            } else {
                *(__half2*)(Ch + (size_t)row * ldc + col) =
                    __halves2half2(__float2half_rn(acc[i][j][0]), __float2half_rn(acc[i][j][1]));
                *(__half2*)(Ch + (size_t)(row + 8) * ldc + col) =
                    __halves2half2(__float2half_rn(acc[i][j][2]), __float2half_rn(acc[i][j][3]));
            }
        }
    }
}

// ============================================================================
// fused conversion kernel: grid 6144 blocks x 256
// ============================================================================
__global__ void k_conv(const float* __restrict__ hid,
                       const float* __restrict__ qr,
                       const float* __restrict__ cb)
{
    __shared__ float ts[32][33];
    const int blk = blockIdx.x;
    const int tid = threadIdx.x;

    if (blk < 4096) {
        int i = blk;                                     // 8 x 64 x 8
        int fb = i & 7, tb = (i >> 3) & 63, bq = i >> 9;
        int b = bq >> 2, q = bq & 3;
        int t0 = tb * 32, f0 = fb * 32;
        int tx = tid & 31, ty = tid >> 5;
#pragma unroll
        for (int r = 0; r < 4; r++) {
            int tt = t0 + ty + r * 8;
            float v = hid[(size_t)b * 2097152 + (size_t)tt * 1024 + q * 256 + f0 + tx];
            ts[ty + r * 8][tx] = v;
            g_Xnt[(size_t)b * 2097152 + (size_t)tt * 1024 + q * 256 + f0 + tx] =
                __float2half_rn(v);
        }
        __syncthreads();
#pragma unroll
        for (int r = 0; r < 4; r++) {
            int f = f0 + ty + r * 8;
            int tw = t0 + tx;
            g_Xt[(size_t)bq * 524288 + (size_t)f * 2048 + tw] =
                __float2half_rn(ts[tx][ty + r * 8]);
        }
    } else if (blk < 5120) {
        int o4 = (blk - 4096) * 256 + tid;               // 262144 float4s
        int aq = o4 >> 14;
        int rem = (o4 << 2) & 65535;
        int e = rem >> 8, f = rem & 255;
        int a = aq >> 2, q = aq & 3;
        float4 v = *(const float4*)(qr + (size_t)a * 262144 + (size_t)e * 1024 + q * 256 + f);
        v.x *= 1024.f; v.y *= 1024.f; v.z *= 1024.f; v.w *= 1024.f;
        ((uint2*)g_Wc)[o4] = pack4H(v);
    } else {
        int i = blk - 5120;                              // 8 x 8 x 16
        int gpb = i & 7, gb = (i >> 3) & 7, aq = i >> 6;
        int a = aq >> 2, q = aq & 3;
        int g0 = gb * 32, gp0 = gpb * 32;
        int tx = tid & 31, ty = tid >> 5;
#pragma unroll
        for (int r = 0; r < 4; r++) {
            int g = g0 + ty + r * 8;
            ts[ty + r * 8][tx] =
                cb[(size_t)a * 262144 + (size_t)(q * 256 + g) * 256 + gp0 + tx] * 1024.f;
        }
        __syncthreads();
#pragma unroll
        for (int r = 0; r < 4; r++) {
            int gp = gp0 + ty + r * 8;
            int gw = g0 + tx;
            g_Ct[(size_t)aq * 65536 + (size_t)gp * 256 + gw] =
                __float2half_rn(ts[tx][ty + r * 8]);
        }
    }
}

// ---- reduce Gram partials (8 chunks, 3 tiles) + mirror + fp16 ---------------
__global__ void k_reduceG()
{
    __shared__ float s[32][33];
    const int sub = blockIdx.x, t = blockIdx.y, bq = blockIdx.z;
    const int r0 = (sub >> 2) * 32, c0 = (sub & 3) * 32;
    const int tx = threadIdx.x & 31, ty = threadIdx.x >> 5;

    const int br = (t == 2) ? 128 : 0;
    const int bc = (t == 0) ? 0 : 128;
    float v[4];
#pragma unroll
    for (int k = 0; k < 4; k++) {
        const int r = r0 + ty + k * 8;
        float a = 0.f;
#pragma unroll
        for (int ch = 0; ch < 8; ch++)
            a += g_Gpart[(size_t)((ch * 8 + bq) * 3 + t) * 16384 + r * 128 + c0 + tx];
        v[k] = a;
        s[ty + k * 8][tx] = a;
    }
#pragma unroll
    for (int k = 0; k < 4; k++) {
        size_t o = (size_t)bq * 65536 + (size_t)(br + r0 + ty + k * 8) * 256 + bc + c0 + tx;
        g_G[o] = __float2half_rn(v[k]);
    }
    if (t == 1) {
        __syncthreads();
#pragma unroll
        for (int k = 0; k < 4; k++) {
            const int orow = 128 + c0 + ty + k * 8;
            const int ocol = r0 + tx;
            g_G[(size_t)bq * 65536 + (size_t)orow * 256 + ocol] =
                __float2half_rn(s[tx][ty + k * 8]);
        }
    }
}

// ---- reduce Pq^T over q, descale 2^-10, fp16 --------------------------------
__global__ void k_reduceP()
{
    int i4 = blockIdx.x * 256 + threadIdx.x;             // 131072 float4s of P^T
    int ba = i4 >> 14;
    int off = i4 & 16383;
    int b = ba >> 2, a = ba & 3;
    size_t base = (size_t)(b * 16 + a * 4) * 16384 + off;
    float4 s = make_float4(0.f, 0.f, 0.f, 0.f);
#pragma unroll
    for (int q = 0; q < 4; q++) {
        float4 v = ((const float4*)g_Pq)[base + (size_t)q * 16384];
        s.x += v.x; s.y += v.y; s.z += v.z; s.w += v.w;
    }
    const float ds = 1.0f / 1024.0f;
    s.x *= ds; s.y *= ds; s.z *= ds; s.w *= ds;
    ((uint2*)g_Pt)[i4] = pack4H(s);
}

// ============================================================================
// GEMM stage kernels (256 threads, 64x128 tiles, 2 CTAs/SM)
// ============================================================================
__global__ void __launch_bounds__(256, 2)
k_s1()  // Gram, symmetric: grid (t*2+h : 6, chunk 8, bq 8) = 384 CTAs, K=256
{
    const int t  = blockIdx.x >> 1;            // 0:(0,0) 1:(0,1) 2:(1,1)
    const int h  = blockIdx.x & 1;             // 64-row half of the m-tile
    const int ch = blockIdx.y, bq = blockIdx.z;
    const int mt = (t == 2) ? 1 : 0;
    const int nt = (t == 0) ? 0 : 1;
    const int k0 = ch * 256;

    size_t xo = (size_t)bq * 524288;
    const __half* A = g_Xt + xo + (size_t)(mt * 128 + h * 64) * 2048 + k0;
    const __half* B = g_Xt + xo + (size_t)nt * 128 * 2048 + k0;
    float* Cf = g_Gpart + (size_t)((ch * 8 + bq) * 3 + t) * 16384 + (size_t)h * 8192;
    gemm_body<0>(A, 2048, B, 2048, 256, Cf, nullptr, 128, 1.0f);
}

__global__ void __launch_bounds__(256, 2)
k_s2()  // T = Ws @ G: grid (8, 1, baq 32) = 256 CTAs
{
    int mt = blockIdx.x >> 1, nt = blockIdx.x & 1;   // mt 0..3 (64-row)
    int baq = blockIdx.z;
    int b = baq >> 4, a = (baq >> 2) & 3, q = baq & 3;
    const __half* A = g_Wc + (size_t)(a * 4 + q) * 65536 + (size_t)mt * 64 * 256;
    const __half* B = g_G + (size_t)(b * 4 + q) * 65536 + (size_t)nt * 128 * 256;
    __half* Ch = g_T + (size_t)baq * 65536 + (size_t)mt * 64 * 256 + nt * 128;
    gemm_body<1>(A, 256, B, 256, 256, nullptr, Ch, 256, 1.0f);
}

__global__ void __launch_bounds__(256, 2)
k_s3()  // Pq^T = Cs_t @ T^T: grid (8, 1, baq 32) = 256 CTAs
{
    int mt = blockIdx.x >> 1, nt = blockIdx.x & 1;
    int baq = blockIdx.z;
    int a = (baq >> 2) & 3, q = baq & 3;
    const __half* A = g_Ct + (size_t)(a * 4 + q) * 65536 + (size_t)mt * 64 * 256;
    const __half* B = g_T + (size_t)baq * 65536 + (size_t)nt * 128 * 256;
    float* Cf = g_Pq + (size_t)baq * 65536 + (size_t)mt * 64 * 256 + nt * 128;
    gemm_body<0>(A, 256, B, 256, 256, Cf, nullptr, 256, 1.0f);
}

__global__ void __launch_bounds__(256, 2)
k_s4(float* __restrict__ out)  // out = 2^-10 * X @ P: grid (64, 1, ba 8) = 512
{
    int mt = blockIdx.x >> 1, nt = blockIdx.x & 1;   // mt 0..31 (64-row)
    int ba = blockIdx.z;
    int b = ba >> 2, a = ba & 3;
    const __half* A = g_Xnt + (size_t)b * 2097152 + (size_t)mt * 64 * 1024 + a * 256;
    const __half* B = g_Pt + (size_t)ba * 65536 + (size_t)nt * 128 * 256;
    float* Cf = out + (size_t)b * 2097152 + (size_t)mt * 64 * 1024 + a * 256 + nt * 128;
    gemm_body<0>(A, 1024, B, 256, 256, Cf, nullptr, 1024, 1.0f / 1024.0f);
}

// ============================================================================
extern "C" void kernel_launch(void* const* d_in, const int* in_sizes, int n_in,
                              void* d_out, int out_size)
{
    const float* hidden    = (const float*)d_in[0];  // [2,2048,1024]
    const float* queries   = (const float*)d_in[1];  // [4,256,1024]
    const float* combiners = (const float*)d_in[2];  // [4,1024,256]
    float* out = (float*)d_out;
    (void)in_sizes; (void)n_in; (void)out_size;

    cudaFuncSetAttribute(k_s1, cudaFuncAttributeMaxDynamicSharedMemorySize, SMEM_DYN);
    cudaFuncSetAttribute(k_s2, cudaFuncAttributeMaxDynamicSharedMemorySize, SMEM_DYN);
    cudaFuncSetAttribute(k_s3, cudaFuncAttributeMaxDynamicSharedMemorySize, SMEM_DYN);
    cudaFuncSetAttribute(k_s4, cudaFuncAttributeMaxDynamicSharedMemorySize, SMEM_DYN);

    k_conv<<<6144, 256>>>(hidden, queries, combiners);
    k_s1<<<dim3(6, 8, 8), 256, SMEM_DYN>>>();
    k_reduceG<<<dim3(16, 3, 8), 256>>>();
    k_s2<<<dim3(8, 1, 32), 256, SMEM_DYN>>>();
    k_s3<<<dim3(8, 1, 32), 256, SMEM_DYN>>>();
    k_reduceP<<<512, 256>>>();
    k_s4<<<dim3(64, 1, 8), 256, SMEM_DYN>>>(out);
}

// round 10
// speedup vs baseline: 1.1698x; 1.1698x over previous
#include <cuda_runtime.h>
#include <cuda_fp16.h>
#include <cstdint>

// ============================================================================
// DenseAttention via Gram reassociation:
//   G[b,q]  = X_{b,q}^T X_{b,q}             (symmetric => compute 3 of 4 tiles)
//   T[b,a,q]= (1024*W_{a,q}) @ G[b,q]
//   Pq      = T @ (1024*C_{a,q})^T-layout ;  P[b,a] = 2^-20 ... (descale 2^-10)
//   out     = 2^-10 * X_{b,a} @ P[b,a]
// Single-pass fp16, fp32 accumulate (rel_err 5.25e-4, calibrated R7/R8).
// R10: s2+s3 FUSED into k_s23 — T-tile lives in SMEM (fp16, same precision as
// the old gmem round-trip). Per-stage fixed overhead (~10k cyc) eliminated
// once; kernel count 7 -> 6.
// ============================================================================

#define HH 65536

// ---------------- scratch (static device globals; no allocation) ------------
__device__ __align__(256) __half g_Xt[8 * 256 * 2048];      // [bq][f][t]
__device__ __align__(256) __half g_Xnt[2 * 2048 * 1024];    // [b][t][e]
__device__ __align__(256) __half g_Wc[16 * HH];             // [aq][e][f] *1024
__device__ __align__(256) __half g_Ct[16 * HH];             // [aq][g'][g] *1024
__device__ __align__(256) float  g_Gpart[6 * 8 * 3 * 16384];// [chunk][bq][tile]
__device__ __align__(256) __half g_G[8 * HH];               // [bq][f][g]
__device__ __align__(256) float  g_Pq[32 * HH];             // [baq][e][g']
__device__ __align__(256) __half g_Pt[8 * HH];              // [ba][g'][e]

// ---------------- PTX helpers ------------------------------------------------
__device__ __forceinline__ uint32_t smem_u32(const void* p) {
    uint32_t a;
    asm("{ .reg .u64 t; cvta.to.shared.u64 t, %1; cvt.u32.u64 %0, t; }" : "=r"(a) : "l"(p));
    return a;
}
__device__ __forceinline__ void cpa16(uint32_t s, const void* g) {
    asm volatile("cp.async.cg.shared.global [%0], [%1], 16;" :: "r"(s), "l"(g));
}
#define CP_COMMIT() asm volatile("cp.async.commit_group;" ::: "memory")
#define CP_WAIT(n)  asm volatile("cp.async.wait_group %0;" :: "n"(n) : "memory")

#define LDSM_X4(r, addr) \
    asm volatile("ldmatrix.sync.aligned.m8n8.x4.shared.b16 {%0,%1,%2,%3}, [%4];" \
        : "=r"((r)[0]), "=r"((r)[1]), "=r"((r)[2]), "=r"((r)[3]) : "r"(addr))

#define MMA_F16(d, a, b0, b1) \
    asm volatile("mma.sync.aligned.m16n8k16.row.col.f32.f16.f16.f32 " \
        "{%0,%1,%2,%3}, {%4,%5,%6,%7}, {%8,%9}, {%0,%1,%2,%3};" \
        : "+f"((d)[0]), "+f"((d)[1]), "+f"((d)[2]), "+f"((d)[3]) \
        : "r"((a)[0]), "r"((a)[1]), "r"((a)[2]), "r"((a)[3]), "r"(b0), "r"(b1))

__device__ __forceinline__ uint2 pack4H(float4 v) {
    union { __half b[4]; uint2 u; } Hq;
    Hq.b[0] = __float2half_rn(v.x); Hq.b[1] = __float2half_rn(v.y);
    Hq.b[2] = __float2half_rn(v.z); Hq.b[3] = __float2half_rn(v.w);
    return Hq.u;
}

// ============================================================================
// Generic 128x128 tile GEMM (s1, s4): 256 threads, 8 warps 4Mx2N (32x64 warp
// tile), BK=128 double-buffered cp.async, fp16 single-pass, fp32 accum.
// Row pitch 272B (16 mod 128 => conflict-free ldmatrix phasing, validated).
// ============================================================================
#define ROWB   272
#define T_A    0
#define T_B    34816
#define BUFSZ  69632
#define SMEM_G (2 * BUFSZ)

__device__ __forceinline__ void gemm128(
    const __half* __restrict__ A, int lda,
    const __half* __restrict__ B, int ldb,
    int K, float* __restrict__ Cf, int ldc, float outScale)
{
    extern __shared__ char smem[];
    const uint32_t sb  = smem_u32(smem);
    const int tid  = threadIdx.x;
    const int lane = tid & 31;
    const int wid  = tid >> 5;
    const int m0   = (wid >> 1) * 32;
    const int n0   = (wid & 1) * 64;

    const uint32_t aoff = (uint32_t)(m0 + (lane & 15)) * ROWB + ((lane >> 4) << 4);
    const uint32_t boff = (uint32_t)(n0 + ((lane >> 4) << 3) + (lane & 7)) * ROWB
                        + ((lane & 8) ? 16u : 0u);

    float acc[2][8][4];
#pragma unroll
    for (int i = 0; i < 2; i++)
#pragma unroll
        for (int j = 0; j < 8; j++)
#pragma unroll
            for (int r = 0; r < 4; r++) acc[i][j][r] = 0.0f;

    auto load_chunk = [&](int c) {
        const uint32_t bo = sb + (uint32_t)(c & 1) * BUFSZ;
        const int k0 = c << 7;
#pragma unroll
        for (int i = 0; i < 8; i++) {
            int v = i * 256 + tid;
            int r = v >> 4, j = v & 15;
            uint32_t so = (uint32_t)r * ROWB + (uint32_t)j * 16;
            cpa16(bo + T_A + so, A + (size_t)r * lda + k0 + j * 8);
            cpa16(bo + T_B + so, B + (size_t)r * ldb + k0 + j * 8);
        }
    };

    const int NC = K >> 7;
    load_chunk(0);
    CP_COMMIT();

#pragma unroll 1
    for (int c = 0; c < NC; c++) {
        if (c < NC - 1) { load_chunk(c + 1); CP_COMMIT(); CP_WAIT(1); }
        else            { CP_WAIT(0); }
        __syncthreads();

        const uint32_t bo = sb + (uint32_t)(c & 1) * BUFSZ;
        const uint32_t aP = bo + T_A + aoff;
        const uint32_t bP = bo + T_B + boff;

#pragma unroll
        for (int ks = 0; ks < 8; ks++) {
            const uint32_t ko = (uint32_t)ks * 32;
            uint32_t a0[4], a1[4];
            LDSM_X4(a0, aP + ko);
            LDSM_X4(a1, aP + 16 * ROWB + ko);
            uint32_t br[4][4];
#pragma unroll
            for (int p = 0; p < 4; p++)
                LDSM_X4(br[p], bP + (uint32_t)p * 16 * ROWB + ko);
#pragma unroll
            for (int j = 0; j < 8; j++)
                MMA_F16(acc[0][j], a0, br[j >> 1][(j & 1) * 2], br[j >> 1][(j & 1) * 2 + 1]);
#pragma unroll
            for (int j = 0; j < 8; j++)
                MMA_F16(acc[1][j], a1, br[j >> 1][(j & 1) * 2], br[j >> 1][(j & 1) * 2 + 1]);
        }
        __syncthreads();
    }

    const int rr = lane >> 2;
    const int cc = (lane & 3) * 2;
#pragma unroll
    for (int i = 0; i < 2; i++) {
#pragma unroll
        for (int j = 0; j < 8; j++) {
            const int row = m0 + i * 16 + rr;
            const int col = n0 + j * 8 + cc;
            float* p = Cf + (size_t)row * ldc + col;
            *(float2*)p = make_float2(acc[i][j][0] * outScale, acc[i][j][1] * outScale);
            *(float2*)(p + (size_t)8 * ldc) =
                make_float2(acc[i][j][2] * outScale, acc[i][j][3] * outScale);
        }
    }
}

// ============================================================================
// FUSED s2+s3 kernel: 64x256 tiles, 256 threads (8 warps: 2M x 4N, warp 32x64).
// Phase 1: T_tile[64 e][256 g] = Ws[e][f] @ G[f][g]   (B = G rows, symmetric)
//          -> fp16 into SMEM (row pitch 528B).
// Phase 2: Pq[64 e][256 g'] = T_tile[e][g] @ Ct[g'][g] (A from SMEM, B gmem).
// SMEM: 2 x (A 64x272 + B 256x272) = 174080  +  T 64x528 = 33792 -> 207872.
// ============================================================================
#define BUF23   87040
#define B23_OFF 17408
#define T23_OFF 174080
#define ROWB2   528
#define SMEM_23 207872

__global__ void __launch_bounds__(256)
k_s23()  // grid (et 4, 1, baq 32) = 128 CTAs
{
    extern __shared__ char smem[];
    const uint32_t sb  = smem_u32(smem);
    const int tid  = threadIdx.x;
    const int lane = tid & 31;
    const int wid  = tid >> 5;
    const int m0   = (wid & 1) * 32;      // 2 M-warps
    const int n0   = (wid >> 1) * 64;     // 4 N-warps
    const int et   = blockIdx.x;
    const int baq  = blockIdx.z;
    const int b = baq >> 4, a = (baq >> 2) & 3, q = baq & 3;
    const int aq = a * 4 + q, bq = b * 4 + q;

    const __half* Aw = g_Wc + (size_t)aq * 65536 + (size_t)et * 64 * 256; // [64][256]
    const __half* Bg = g_G  + (size_t)bq * 65536;                          // [256][256]
    const __half* Bc = g_Ct + (size_t)aq * 65536;                          // [256][256]

    const uint32_t aoff  = (uint32_t)(m0 + (lane & 15)) * ROWB + ((lane >> 4) << 4);
    const uint32_t aoff2 = (uint32_t)(m0 + (lane & 15)) * ROWB2 + ((lane >> 4) << 4);
    const uint32_t boff  = (uint32_t)(n0 + ((lane >> 4) << 3) + (lane & 7)) * ROWB
                         + ((lane & 8) ? 16u : 0u);
    const int rr = lane >> 2;
    const int cc = (lane & 3) * 2;

    float acc[2][8][4];

    // ---- generic BK=128 chunk loader: A 64 rows (opt), B 256 rows ----------
    auto load_A = [&](int c, const __half* A) {
        const uint32_t bo = sb + (uint32_t)(c & 1) * BUF23;
        const int k0 = c << 7;
#pragma unroll
        for (int i = 0; i < 4; i++) {
            int v = i * 256 + tid;
            int r = v >> 4, j = v & 15;
            cpa16(bo + (uint32_t)r * ROWB + (uint32_t)j * 16,
                  A + (size_t)r * 256 + k0 + j * 8);
        }
    };
    auto load_B = [&](int c, const __half* B) {
        const uint32_t bo = sb + (uint32_t)(c & 1) * BUF23 + B23_OFF;
        const int k0 = c << 7;
#pragma unroll
        for (int i = 0; i < 16; i++) {
            int v = i * 256 + tid;
            int r = v >> 4, j = v & 15;
            cpa16(bo + (uint32_t)r * ROWB + (uint32_t)j * 16,
                  B + (size_t)r * 256 + k0 + j * 8);
        }
    };
    auto zero_acc = [&]() {
#pragma unroll
        for (int i = 0; i < 2; i++)
#pragma unroll
            for (int j = 0; j < 8; j++)
#pragma unroll
                for (int r = 0; r < 4; r++) acc[i][j][r] = 0.0f;
    };
    auto mma_chunk_smemA = [&](uint32_t aP, uint32_t arowb, uint32_t bP) {
#pragma unroll
        for (int ks = 0; ks < 8; ks++) {
            const uint32_t ko = (uint32_t)ks * 32;
            uint32_t a0[4], a1[4];
            LDSM_X4(a0, aP + ko);
            LDSM_X4(a1, aP + 16 * arowb + ko);
            uint32_t br[4][4];
#pragma unroll
            for (int p = 0; p < 4; p++)
                LDSM_X4(br[p], bP + (uint32_t)p * 16 * ROWB + ko);
#pragma unroll
            for (int j = 0; j < 8; j++)
                MMA_F16(acc[0][j], a0, br[j >> 1][(j & 1) * 2], br[j >> 1][(j & 1) * 2 + 1]);
#pragma unroll
            for (int j = 0; j < 8; j++)
                MMA_F16(acc[1][j], a1, br[j >> 1][(j & 1) * 2], br[j >> 1][(j & 1) * 2 + 1]);
        }
    };

    // ================= phase 1: T_tile = Ws @ G =============================
    zero_acc();
    load_A(0, Aw); load_B(0, Bg); CP_COMMIT();
    load_A(1, Aw); load_B(1, Bg); CP_COMMIT();
    CP_WAIT(1);
    __syncthreads();
    {
        const uint32_t bo = sb;
        mma_chunk_smemA(bo + aoff, ROWB, bo + B23_OFF + boff);
    }
    CP_WAIT(0);
    __syncthreads();
    {
        const uint32_t bo = sb + BUF23;
        mma_chunk_smemA(bo + aoff, ROWB, bo + B23_OFF + boff);
    }
    __syncthreads();

    // prefetch phase-2 chunk 0 (Ct) while writing T epilogue
    load_B(0, Bc); CP_COMMIT();

    // T epilogue: fp16 into SMEM at T23_OFF, row pitch 528B
    {
        char* Tb = smem + T23_OFF;
#pragma unroll
        for (int i = 0; i < 2; i++) {
#pragma unroll
            for (int j = 0; j < 8; j++) {
                const int row = m0 + i * 16 + rr;
                const int col = n0 + j * 8 + cc;
                *(__half2*)(Tb + (size_t)row * ROWB2 + col * 2) =
                    __halves2half2(__float2half_rn(acc[i][j][0]), __float2half_rn(acc[i][j][1]));
                *(__half2*)(Tb + (size_t)(row + 8) * ROWB2 + col * 2) =
                    __halves2half2(__float2half_rn(acc[i][j][2]), __float2half_rn(acc[i][j][3]));
            }
        }
    }

    // ================= phase 2: Pq = T_tile @ Ct^T ==========================
    zero_acc();
    load_B(1, Bc); CP_COMMIT();
    CP_WAIT(1);
    __syncthreads();   // T_smem ready + Ct chunk 0 ready
    {
        const uint32_t aP = sb + T23_OFF + aoff2;          // k0 = 0
        mma_chunk_smemA(aP, ROWB2, sb + B23_OFF + boff);
    }
    CP_WAIT(0);
    __syncthreads();
    {
        const uint32_t aP = sb + T23_OFF + aoff2 + 256;    // k0 = 128 halves
        mma_chunk_smemA(aP, ROWB2, sb + BUF23 + B23_OFF + boff);
    }

    // epilogue: Pq fp32 [baq][e][g']
    float* Cf = g_Pq + (size_t)baq * 65536 + (size_t)et * 64 * 256;
#pragma unroll
    for (int i = 0; i < 2; i++) {
#pragma unroll
        for (int j = 0; j < 8; j++) {
            const int row = m0 + i * 16 + rr;
            const int col = n0 + j * 8 + cc;
            float* p = Cf + (size_t)row * 256 + col;
            *(float2*)p = make_float2(acc[i][j][0], acc[i][j][1]);
            *(float2*)(p + 8 * 256) = make_float2(acc[i][j][2], acc[i][j][3]);
        }
    }
}

// ============================================================================
// fused conversion kernel: grid 6144 blocks x 256
// ============================================================================
__global__ void k_conv(const float* __restrict__ hid,
                       const float* __restrict__ qr,
                       const float* __restrict__ cb)
{
    __shared__ float ts[32][33];
    const int blk = blockIdx.x;
    const int tid = threadIdx.x;

    if (blk < 4096) {
        int i = blk;                                     // 8 x 64 x 8
        int fb = i & 7, tb = (i >> 3) & 63, bq = i >> 9;
        int b = bq >> 2, q = bq & 3;
        int t0 = tb * 32, f0 = fb * 32;
        int tx = tid & 31, ty = tid >> 5;
#pragma unroll
        for (int r = 0; r < 4; r++) {
            int tt = t0 + ty + r * 8;
            float v = hid[(size_t)b * 2097152 + (size_t)tt * 1024 + q * 256 + f0 + tx];
            ts[ty + r * 8][tx] = v;
            g_Xnt[(size_t)b * 2097152 + (size_t)tt * 1024 + q * 256 + f0 + tx] =
                __float2half_rn(v);
        }
        __syncthreads();
#pragma unroll
        for (int r = 0; r < 4; r++) {
            int f = f0 + ty + r * 8;
            int tw = t0 + tx;
            g_Xt[(size_t)bq * 524288 + (size_t)f * 2048 + tw] =
                __float2half_rn(ts[tx][ty + r * 8]);
        }
    } else if (blk < 5120) {
        int o4 = (blk - 4096) * 256 + tid;               // 262144 float4s
        int aq = o4 >> 14;
        int rem = (o4 << 2) & 65535;
        int e = rem >> 8, f = rem & 255;
        int a = aq >> 2, q = aq & 3;
        float4 v = *(const float4*)(qr + (size_t)a * 262144 + (size_t)e * 1024 + q * 256 + f);
        v.x *= 1024.f; v.y *= 1024.f; v.z *= 1024.f; v.w *= 1024.f;
        ((uint2*)g_Wc)[o4] = pack4H(v);
    } else {
        int i = blk - 5120;                              // 8 x 8 x 16
        int gpb = i & 7, gb = (i >> 3) & 7, aq = i >> 6;
        int a = aq >> 2, q = aq & 3;
        int g0 = gb * 32, gp0 = gpb * 32;
        int tx = tid & 31, ty = tid >> 5;
#pragma unroll
        for (int r = 0; r < 4; r++) {
            int g = g0 + ty + r * 8;
            ts[ty + r * 8][tx] =
                cb[(size_t)a * 262144 + (size_t)(q * 256 + g) * 256 + gp0 + tx] * 1024.f;
        }
        __syncthreads();
#pragma unroll
        for (int r = 0; r < 4; r++) {
            int gp = gp0 + ty + r * 8;
            int gw = g0 + tx;
            g_Ct[(size_t)aq * 65536 + (size_t)gp * 256 + gw] =
                __float2half_rn(ts[tx][ty + r * 8]);
        }
    }
}

// ---- reduce Gram partials (6 chunks, 3 tiles) + mirror + fp16 ---------------
__global__ void k_reduceG()
{
    __shared__ float s[32][33];
    const int sub = blockIdx.x, t = blockIdx.y, bq = blockIdx.z;
    const int r0 = (sub >> 2) * 32, c0 = (sub & 3) * 32;
    const int tx = threadIdx.x & 31, ty = threadIdx.x >> 5;

    const int br = (t == 2) ? 128 : 0;
    const int bc = (t == 0) ? 0 : 128;
    float v[4];
#pragma unroll
    for (int k = 0; k < 4; k++) {
        const int r = r0 + ty + k * 8;
        float a = 0.f;
#pragma unroll
        for (int ch = 0; ch < 6; ch++)
            a += g_Gpart[(size_t)((ch * 8 + bq) * 3 + t) * 16384 + r * 128 + c0 + tx];
        v[k] = a;
        s[ty + k * 8][tx] = a;
    }
#pragma unroll
    for (int k = 0; k < 4; k++) {
        size_t o = (size_t)bq * 65536 + (size_t)(br + r0 + ty + k * 8) * 256 + bc + c0 + tx;
        g_G[o] = __float2half_rn(v[k]);
    }
    if (t == 1) {
        __syncthreads();
#pragma unroll
        for (int k = 0; k < 4; k++) {
            const int orow = 128 + c0 + ty + k * 8;
            const int ocol = r0 + tx;
            g_G[(size_t)bq * 65536 + (size_t)orow * 256 + ocol] =
                __float2half_rn(s[tx][ty + k * 8]);
        }
    }
}

// ---- reduce Pq over q + transpose + descale 2^-10 + fp16 --------------------
// Pq layout [baq][e][g'] -> Pt [ba][g'][e].  grid (8, 8, 8), 256 thr.
__global__ void k_reduceP()
{
    __shared__ float t[32][33];
    const int ba = blockIdx.z, b = ba >> 2, a = ba & 3;
    const int e0 = blockIdx.y * 32, gp0 = blockIdx.x * 32;
    const int tx = threadIdx.x & 31, ty = threadIdx.x >> 5;
#pragma unroll
    for (int r = 0; r < 4; r++) {
        const int e = e0 + ty + r * 8;
        float s = 0.f;
#pragma unroll
        for (int q = 0; q < 4; q++)
            s += g_Pq[(size_t)(b * 16 + a * 4 + q) * 65536 + (size_t)e * 256 + gp0 + tx];
        t[ty + r * 8][tx] = s;
    }
    __syncthreads();
    const float ds = 1.0f / 1024.0f;
#pragma unroll
    for (int r = 0; r < 4; r++) {
        const int gp = gp0 + ty + r * 8;
        const int ew = e0 + tx;
        g_Pt[(size_t)ba * 65536 + (size_t)gp * 256 + ew] =
            __float2half_rn(t[tx][ty + r * 8] * ds);
    }
}

// ============================================================================
// s1 / s4 stage kernels
// ============================================================================
__global__ void __launch_bounds__(256)
k_s1()  // Gram, symmetric: grid (tile 3, chunk 6, bq 8) = 144 CTAs
{
    const int t  = blockIdx.x;                 // 0:(0,0) 1:(0,1) 2:(1,1)
    const int ch = blockIdx.y, bq = blockIdx.z;
    const int mt = (t == 2) ? 1 : 0;
    const int nt = (t == 0) ? 0 : 1;
    const int k0 = (ch < 4) ? ch * 384 : 1536 + (ch - 4) * 256;
    const int K  = (ch < 4) ? 384 : 256;

    size_t xo = (size_t)bq * 524288;
    const __half* A = g_Xt + xo + (size_t)mt * 128 * 2048 + k0;
    const __half* B = g_Xt + xo + (size_t)nt * 128 * 2048 + k0;
    float* Cf = g_Gpart + (size_t)((ch * 8 + bq) * 3 + t) * 16384;
    gemm128(A, 2048, B, 2048, K, Cf, 128, 1.0f);
}

__global__ void __launch_bounds__(256)
k_s4(float* __restrict__ out)  // out = 2^-10 * X @ P: grid (tile 32, 1, ba 8)
{
    int mt = blockIdx.x >> 1, nt = blockIdx.x & 1;
    int ba = blockIdx.z;
    int b = ba >> 2, a = ba & 3;
    const __half* A = g_Xnt + (size_t)b * 2097152 + (size_t)mt * 128 * 1024 + a * 256;
    const __half* B = g_Pt + (size_t)ba * 65536 + (size_t)nt * 128 * 256;
    float* Cf = out + (size_t)b * 2097152 + (size_t)mt * 128 * 1024 + a * 256 + nt * 128;
    gemm128(A, 1024, B, 256, 256, Cf, 1024, 1.0f / 1024.0f);
}

// ============================================================================
extern "C" void kernel_launch(void* const* d_in, const int* in_sizes, int n_in,
                              void* d_out, int out_size)
{
    const float* hidden    = (const float*)d_in[0];  // [2,2048,1024]
    const float* queries   = (const float*)d_in[1];  // [4,256,1024]
    const float* combiners = (const float*)d_in[2];  // [4,1024,256]
    float* out = (float*)d_out;
    (void)in_sizes; (void)n_in; (void)out_size;

    cudaFuncSetAttribute(k_s1,  cudaFuncAttributeMaxDynamicSharedMemorySize, SMEM_G);
    cudaFuncSetAttribute(k_s23, cudaFuncAttributeMaxDynamicSharedMemorySize, SMEM_23);
    cudaFuncSetAttribute(k_s4,  cudaFuncAttributeMaxDynamicSharedMemorySize, SMEM_G);

    k_conv<<<6144, 256>>>(hidden, queries, combiners);
    k_s1<<<dim3(3, 6, 8), 256, SMEM_G>>>();
    k_reduceG<<<dim3(16, 3, 8), 256>>>();
    k_s23<<<dim3(4, 1, 32), 256, SMEM_23>>>();
    k_reduceP<<<dim3(8, 8, 8), 256>>>();
    k_s4<<<dim3(32, 1, 8), 256, SMEM_G>>>(out);
}